// round 4
// baseline (speedup 1.0000x reference)
#include <cuda_runtime.h>

// Problem constants (fixed by setup_inputs)
#define BS      64
#define C_TS    128
#define C_CTS   256
#define T_LEN   2048
#define N_CAT   32
#define N_CONT  64

#define MASK_P    0.15f
#define REPLACE_P 0.80f
#define RAND_HI   0.90f   // REPLACE_P + RANDOM_P

// Decision codes (int16): -2 keep, -1 zero, >=0 swap index within row
#define CODE_KEEP  (-2)
#define CODE_ZERO  (-1)

// Scratch: compact per-(b,t) decision codes (256 KB each, L2-resident)
__device__ short g_code_ts [BS * T_LEN];
__device__ short g_code_cts[BS * T_LEN];

// ---------------------------------------------------------------------------
// Precompute: encode decisions for both TS tensors. Thread handles 8 t.
// ---------------------------------------------------------------------------
#define DEC_N        (BS * T_LEN)                       // 131072 per tensor
#define DEC_THREADS  256
#define DEC_PER_T    8
#define DEC_BLOCKS   ((2 * DEC_N) / (DEC_THREADS * DEC_PER_T))   // 128

__device__ __forceinline__ short decide(float um, float ua, int ridx)
{
    if (um < MASK_P) {
        if (ua < REPLACE_P) return (short)CODE_ZERO;
        if (ua < RAND_HI)   return (short)ridx;
    }
    return (short)CODE_KEEP;
}

__global__ void __launch_bounds__(DEC_THREADS)
precompute_kernel(const float* __restrict__ u_ts_mask,
                  const float* __restrict__ u_ts_act,
                  const int*   __restrict__ r_ts_idx,
                  const float* __restrict__ u_cts_mask,
                  const float* __restrict__ u_cts_act,
                  const int*   __restrict__ r_cts_idx)
{
    long base = ((long)blockIdx.x * DEC_THREADS + threadIdx.x) * DEC_PER_T;
    const float* um;
    const float* ua;
    const int*   ri;
    short* code;
    long off;
    if (base < DEC_N) { um = u_ts_mask;  ua = u_ts_act;  ri = r_ts_idx;  code = g_code_ts;  off = base; }
    else              { um = u_cts_mask; ua = u_cts_act; ri = r_cts_idx; code = g_code_cts; off = base - DEC_N; }

    float4 m0 = *(const float4*)(um + off);
    float4 m1 = *(const float4*)(um + off + 4);
    float4 a0 = *(const float4*)(ua + off);
    float4 a1 = *(const float4*)(ua + off + 4);
    int4   r0 = *(const int4*)  (ri + off);
    int4   r1 = *(const int4*)  (ri + off + 4);

    short c[8];
    c[0] = decide(m0.x, a0.x, r0.x);
    c[1] = decide(m0.y, a0.y, r0.y);
    c[2] = decide(m0.z, a0.z, r0.z);
    c[3] = decide(m0.w, a0.w, r0.w);
    c[4] = decide(m1.x, a1.x, r1.x);
    c[5] = decide(m1.y, a1.y, r1.y);
    c[6] = decide(m1.z, a1.z, r1.z);
    c[7] = decide(m1.w, a1.w, r1.w);

    int4 packed;
    packed.x = (int)(unsigned short)c[0] | ((int)(unsigned short)c[1] << 16);
    packed.y = (int)(unsigned short)c[2] | ((int)(unsigned short)c[3] << 16);
    packed.z = (int)(unsigned short)c[4] | ((int)(unsigned short)c[5] << 16);
    packed.w = (int)(unsigned short)c[6] | ((int)(unsigned short)c[7] << 16);
    *(int4*)(code + off) = packed;
}

// ---------------------------------------------------------------------------
// Fused streaming kernel. One block = one (b, c) row of 2048 floats.
// Thread tid handles t = tid*4..tid*4+3 and t = 1024+tid*4..1024+tid*4+3.
// Every load/store instruction is fully coalesced (block covers contiguous 4KB).
// ---------------------------------------------------------------------------
#define MAIN_THREADS 256
#define TS_BLOCKS    (BS * C_TS)     // 8192
#define CTS_BLOCKS   (BS * C_CTS)    // 16384
#define HALF         (T_LEN / 2)     // 1024

__device__ __forceinline__ float4 apply4(float4 x, int2 pc, const float* __restrict__ row)
{
    short c[4];
    c[0] = (short)(pc.x & 0xFFFF); c[1] = (short)(pc.x >> 16);
    c[2] = (short)(pc.y & 0xFFFF); c[3] = (short)(pc.y >> 16);
    float v[4] = {x.x, x.y, x.z, x.w};
#pragma unroll
    for (int i = 0; i < 4; i++) {
        short ci = c[i];
        if (ci != (short)CODE_KEEP) {
            v[i] = (ci >= 0) ? __ldg(row + ci) : 0.0f;
        }
    }
    return make_float4(v[0], v[1], v[2], v[3]);
}

__global__ void __launch_bounds__(MAIN_THREADS)
fused_mask_kernel(const float* __restrict__ x_ts,
                  float* __restrict__ out_ts,
                  const float* __restrict__ x_cts,
                  float* __restrict__ out_cts,
                  const int*   __restrict__ x_cat,
                  const float* __restrict__ x_cont,
                  const float* __restrict__ u_cat_mask,
                  const float* __restrict__ u_cat_act,
                  const int*   __restrict__ r_cat_val,
                  const float* __restrict__ u_cont_mask,
                  const float* __restrict__ u_cont_act,
                  const int*   __restrict__ r_cont_idx,
                  float* __restrict__ out_cat,
                  float* __restrict__ out_cont)
{
    long blk = blockIdx.x;
    int tid = threadIdx.x;

    if (blk < TS_BLOCKS + CTS_BLOCKS) {
        const float* x;
        float* out;
        const short* code;
        int b;
        long bc;
        if (blk < TS_BLOCKS) {
            x = x_ts; out = out_ts; code = g_code_ts;
            bc = blk;  b = (int)(blk >> 7);          // / C_TS
        } else {
            bc = blk - TS_BLOCKS;
            x = x_cts; out = out_cts; code = g_code_cts;
            b = (int)(bc >> 8);                      // / C_CTS
        }

        const float* row  = x   + bc * T_LEN;
        float*       orow = out + bc * T_LEN;
        const short* crow = code + (long)b * T_LEN;

        int t0 = tid * 4;           // [0, 1024)
        int t1 = t0 + HALF;         // [1024, 2048)

        // 4 independent loads, all fully coalesced
        float4 x0 = *(const float4*)(row + t0);
        float4 x1 = *(const float4*)(row + t1);
        int2   c0 = *(const int2*)(crow + t0);
        int2   c1 = *(const int2*)(crow + t1);

        *(float4*)(orow + t0) = apply4(x0, c0, row);
        *(float4*)(orow + t1) = apply4(x1, c1, row);
        return;
    }

    // ---- static cat + cont (single tail block, 256 threads) ----
    __shared__ float partial[4][N_CONT];
    __shared__ float means[N_CONT];

    {
        int j = tid & (N_CONT - 1);        // column
        int chunk = tid >> 6;              // 0..3, 16 rows each
        float s = 0.0f;
        for (int b = chunk * 16; b < chunk * 16 + 16; b++)
            s += x_cont[b * N_CONT + j];
        partial[chunk][j] = s;
    }
    __syncthreads();
    if (tid < N_CONT) {
        means[tid] = (partial[0][tid] + partial[1][tid] +
                      partial[2][tid] + partial[3][tid]) * (1.0f / BS);
    }
    __syncthreads();

    // categorical: BS*N_CAT = 2048 elements
    for (int i = tid; i < BS * N_CAT; i += blockDim.x) {
        float um = u_cat_mask[i];
        float ua = u_cat_act[i];
        int v = x_cat[i];
        if (um < MASK_P) {
            if (ua < REPLACE_P)    v = 0;
            else if (ua < RAND_HI) v = r_cat_val[i];
        }
        out_cat[i] = (float)v;
    }

    // continuous: BS*N_CONT = 4096 elements
    for (int i = tid; i < BS * N_CONT; i += blockDim.x) {
        int j = i & (N_CONT - 1);
        float um = u_cont_mask[i];
        float ua = u_cont_act[i];
        float v = x_cont[i];
        if (um < MASK_P) {
            if (ua < REPLACE_P)    v = means[j];
            else if (ua < RAND_HI) v = x_cont[r_cont_idx[i] * N_CONT + j];
        }
        out_cont[i] = v;
    }
}

// ---------------------------------------------------------------------------
// Launch
// ---------------------------------------------------------------------------
extern "C" void kernel_launch(void* const* d_in, const int* in_sizes, int n_in,
                              void* d_out, int out_size)
{
    const float* x_ts     = (const float*)d_in[0];
    const float* x_ts_cat = (const float*)d_in[1];
    const int*   x_cat    = (const int*)  d_in[2];
    const float* x_cont   = (const float*)d_in[3];

    const float* u_ts_mask  = (const float*)d_in[4];
    const float* u_ts_act   = (const float*)d_in[5];
    const int*   r_ts_idx   = (const int*)  d_in[6];
    const float* u_cts_mask = (const float*)d_in[7];
    const float* u_cts_act  = (const float*)d_in[8];
    const int*   r_cts_idx  = (const int*)  d_in[9];

    const float* u_cat_mask = (const float*)d_in[10];
    const float* u_cat_act  = (const float*)d_in[11];
    const int*   r_cat_val  = (const int*)  d_in[12];
    const float* u_cont_mask= (const float*)d_in[13];
    const float* u_cont_act = (const float*)d_in[14];
    const int*   r_cont_idx = (const int*)  d_in[15];

    float* out = (float*)d_out;
    const long TS_ELEMS  = (long)BS * C_TS  * T_LEN;   // 16,777,216
    const long CTS_ELEMS = (long)BS * C_CTS * T_LEN;   // 33,554,432
    float* out_ts   = out;
    float* out_cts  = out + TS_ELEMS;
    float* out_cat  = out + TS_ELEMS + CTS_ELEMS;
    float* out_cont = out_cat + (long)BS * N_CAT;

    precompute_kernel<<<DEC_BLOCKS, DEC_THREADS>>>(
        u_ts_mask, u_ts_act, r_ts_idx,
        u_cts_mask, u_cts_act, r_cts_idx);

    fused_mask_kernel<<<TS_BLOCKS + CTS_BLOCKS + 1, MAIN_THREADS>>>(
        x_ts, out_ts, x_ts_cat, out_cts,
        x_cat, x_cont,
        u_cat_mask, u_cat_act, r_cat_val,
        u_cont_mask, u_cont_act, r_cont_idx,
        out_cat, out_cont);
}